// round 17
// baseline (speedup 1.0000x reference)
#include <cuda_runtime.h>
#include <cstdint>

// Problem constants
#define BB    8
#define FF    6
#define FM1   5          // frames used (1..5)
#define NBUF  5
#define NSLOT 7
#define HH    192
#define WW    192
#define CC    3
#define HW    (HH*WW)    // 36864

#define TPB   256
#define PXT   2                              // pixels per thread (float2)
#define CHUNK_PX (TPB*PXT)                   // 512
#define CHUNKS_PER_IMG (HW/CHUNK_PX)         // 72
#define NIMG  (BB*FM1)                       // 40
#define NCHUNK (NIMG*CHUNKS_PER_IMG)         // 2880 per type
#define GRID_MAIN (2*NCHUNK)                 // 5760 (even=MSE, odd=BCE)

#define EPSF   1e-7f
#define OMEPSF (1.0f - 1e-7f)

__device__ float g_partials[GRID_MAIN];
__device__ unsigned int g_ticket = 0;

__device__ __forceinline__ float2 ld2s(const float* __restrict__ p) {
    return __ldcs(reinterpret_cast<const float2*>(p));
}

__global__ __launch_bounds__(TPB)
void em_main(const float* __restrict__ seg,
             const float* __restrict__ masks,
             const float* __restrict__ rec,
             const float* __restrict__ tgt,
             const float* __restrict__ vis,
             const float* __restrict__ attn,
             float* __restrict__ out)
{
    __shared__ __align__(16) float sC_T[NBUF][8];  // coef table, transposed [n][s], padded
    __shared__ float sA[NBUF];                     // (1/HW)*sum_s attn[s][n]   (BCE only)
    __shared__ float wsum[TPB / 32];
    __shared__ bool  isLast;

    const int tid = (int)threadIdx.x;
    const int bid = (int)blockIdx.x;
    const bool mse = (bid & 1) == 0;
    const int idx   = bid >> 1;                // 0..2879
    const int img   = idx / CHUNKS_PER_IMG;
    const int chunk = idx % CHUNKS_PER_IMG;
    const int b = img / FM1;
    const int f = img % FM1 + 1;               // skip frame 0
    const int base = b*FF + f;
    const int px   = chunk * CHUNK_PX + tid * PXT;

    const float invHW = 1.0f / (float)HW;
    const float Kc    = 0.1f / (float)CC;
    const float scale = mse ? Kc : invHW;

    // coef table: sC_T[n][s] = attn[s][n] * scale  (transposed, padded to 8)
    if (tid < NBUF * 8) {
        int n = tid >> 3, s = tid & 7;
        float a = (s < NSLOT) ? attn[(base*NSLOT + s)*NBUF + n] : 0.0f;
        sC_T[n][s] = a * scale;
    }
    if (!mse && tid >= 64 && tid < 64 + NBUF) {
        int n = tid - 64;
        float sum = 0.0f;
        #pragma unroll
        for (int s = 0; s < NSLOT; s++)
            sum += attn[(base*NSLOT + s)*NBUF + n];
        sA[n] = sum * invHW;
    }

    float acc0 = 0.0f, acc1 = 0.0f;

    if (mse) {
        // ========================== MSE block ==========================
        // independent upfront loads: vis (7) + tgt (3)
        float2 v[NSLOT];
        #pragma unroll
        for (int s = 0; s < NSLOT; s++)
            v[s] = ld2s(vis + (size_t)(base*NSLOT + s)*HW + px);
        float2 tg[CC];
        #pragma unroll
        for (int c = 0; c < CC; c++)
            tg[c] = ld2s(tgt + (size_t)(base*CC + c)*HW + px);

        __syncthreads();   // coef table ready

        float vb0[NSLOT], vb1[NSLOT];
        #pragma unroll
        for (int s = 0; s < NSLOT; s++) {
            vb0[s] = (v[s].x > 0.5f) ? 1.0f : 0.0f;
            vb1[s] = (v[s].y > 0.5f) ? 1.0f : 0.0f;
        }

        float V0[NBUF], V1[NBUF];
        #pragma unroll
        for (int n = 0; n < NBUF; n++) {
            float4 c0 = *reinterpret_cast<const float4*>(&sC_T[n][0]);
            float4 c1 = *reinterpret_cast<const float4*>(&sC_T[n][4]);
            float a0 = vb0[0]*c0.x, a1 = vb1[0]*c0.x;
            a0 = fmaf(vb0[1], c0.y, a0);  a1 = fmaf(vb1[1], c0.y, a1);
            a0 = fmaf(vb0[2], c0.z, a0);  a1 = fmaf(vb1[2], c0.z, a1);
            a0 = fmaf(vb0[3], c0.w, a0);  a1 = fmaf(vb1[3], c0.w, a1);
            a0 = fmaf(vb0[4], c1.x, a0);  a1 = fmaf(vb1[4], c1.x, a1);
            a0 = fmaf(vb0[5], c1.y, a0);  a1 = fmaf(vb1[5], c1.y, a1);
            a0 = fmaf(vb0[6], c1.z, a0);  a1 = fmaf(vb1[6], c1.z, a1);
            V0[n] = a0; V1[n] = a1;
        }

        // stream rec: 15 loads, consumed immediately
        #pragma unroll
        for (int n = 0; n < NBUF; n++) {
            float d20 = 0.0f, d21 = 0.0f;
            #pragma unroll
            for (int c = 0; c < CC; c++) {
                float2 r = ld2s(rec + (size_t)((base*NBUF + n)*CC + c)*HW + px);
                float dd0 = r.x - tg[c].x;
                float dd1 = r.y - tg[c].y;
                d20 = fmaf(dd0, dd0, d20);
                d21 = fmaf(dd1, dd1, d21);
            }
            acc0 = fmaf(V0[n], d20, acc0);
            acc1 = fmaf(V1[n], d21, acc1);
        }
    } else {
        // ========================== BCE block ==========================
        // independent upfront loads: masks (7) + seg (5)
        float2 m[NSLOT];
        #pragma unroll
        for (int s = 0; s < NSLOT; s++)
            m[s] = ld2s(masks + (size_t)(base*NSLOT + s)*HW + px);
        float2 p[NBUF];
        #pragma unroll
        for (int n = 0; n < NBUF; n++)
            p[n] = ld2s(seg + (size_t)(base*NBUF + n)*HW + px);

        __syncthreads();   // coef table + sA ready

        float tb0[NSLOT], tb1[NSLOT];
        #pragma unroll
        for (int s = 0; s < NSLOT; s++) {
            tb0[s] = (m[s].x > 0.5f) ? 1.0f : 0.0f;
            tb1[s] = (m[s].y > 0.5f) ? 1.0f : 0.0f;
        }

        #pragma unroll
        for (int n = 0; n < NBUF; n++) {
            float4 c0 = *reinterpret_cast<const float4*>(&sC_T[n][0]);
            float4 c1 = *reinterpret_cast<const float4*>(&sC_T[n][4]);
            float T0 = tb0[0]*c0.x, T1 = tb1[0]*c0.x;
            T0 = fmaf(tb0[1], c0.y, T0);  T1 = fmaf(tb1[1], c0.y, T1);
            T0 = fmaf(tb0[2], c0.z, T0);  T1 = fmaf(tb1[2], c0.z, T1);
            T0 = fmaf(tb0[3], c0.w, T0);  T1 = fmaf(tb1[3], c0.w, T1);
            T0 = fmaf(tb0[4], c1.x, T0);  T1 = fmaf(tb1[4], c1.x, T1);
            T0 = fmaf(tb0[5], c1.y, T0);  T1 = fmaf(tb1[5], c1.y, T1);
            T0 = fmaf(tb0[6], c1.z, T0);  T1 = fmaf(tb1[6], c1.z, T1);

            const float An = sA[n];
            {
                float pc  = fminf(fmaxf(p[n].x, EPSF), OMEPSF);
                float lp  = __logf(pc);
                float l1m = __logf(1.0f - pc);   // == log1p(-p) in fp32 (Sterbenz)
                acc0 = fmaf(-T0, lp, acc0);
                acc0 = fmaf(T0 - An, l1m, acc0);
            }
            {
                float pc  = fminf(fmaxf(p[n].y, EPSF), OMEPSF);
                float lp  = __logf(pc);
                float l1m = __logf(1.0f - pc);
                acc1 = fmaf(-T1, lp, acc1);
                acc1 = fmaf(T1 - An, l1m, acc1);
            }
        }
    }

    // ================= block reduction =================
    float tot = acc0 + acc1;
    #pragma unroll
    for (int o = 16; o > 0; o >>= 1)
        tot += __shfl_down_sync(0xffffffffu, tot, o);

    if ((tid & 31) == 0) wsum[tid >> 5] = tot;
    __syncthreads();

    if (tid == 0) {
        float s = 0.0f;
        #pragma unroll
        for (int i = 0; i < TPB / 32; i++) s += wsum[i];
        g_partials[bid] = s;
        __threadfence();
        unsigned prev = atomicAdd(&g_ticket, 1u);
        isLast = (prev == GRID_MAIN - 1);
    }
    __syncthreads();

    // ================= last block: final deterministic reduction =================
    if (isLast) {
        float v0 = 0.0f, v1 = 0.0f;
        #pragma unroll 1
        for (int i = tid; i < GRID_MAIN; i += TPB * 2) {
            v0 += g_partials[i];
            float x = (i + TPB < GRID_MAIN) ? g_partials[i + TPB] : 0.0f;
            v1 += x;
        }
        float v = v0 + v1;
        #pragma unroll
        for (int o = 16; o > 0; o >>= 1)
            v += __shfl_down_sync(0xffffffffu, v, o);
        if ((tid & 31) == 0) wsum[tid >> 5] = v;
        __syncthreads();
        if (tid == 0) {
            float s = 0.0f;
            #pragma unroll
            for (int i = 0; i < TPB / 32; i++) s += wsum[i];
            // total / (B*(F-1)*NB*NS) * LOSS_WEIGHT = total * 20/1400
            out[0] = s * (20.0f / 1400.0f);
            atomicExch(&g_ticket, 0u);          // reset for next graph replay
        }
    }
}

extern "C" void kernel_launch(void* const* d_in, const int* in_sizes, int n_in,
                              void* d_out, int out_size)
{
    const float* seg   = (const float*)d_in[0];  // segmentations   [B,F,NB,H,W]
    const float* masks = (const float*)d_in[1];  // masks           [B,F,NS,H,W]
    const float* rec   = (const float*)d_in[2];  // reconstructions [B,F,NB,C,H,W]
    const float* tgt   = (const float*)d_in[3];  // rec_tgt         [B,F,C,H,W]
    const float* vis   = (const float*)d_in[4];  // masks_vis       [B,F,NS,H,W]
    const float* attn  = (const float*)d_in[5];  // attn_index      [B,F,NS,NB]
    (void)in_sizes; (void)n_in; (void)out_size;

    em_main<<<GRID_MAIN, TPB>>>(seg, masks, rec, tgt, vis, attn, (float*)d_out);
}